// round 3
// baseline (speedup 1.0000x reference)
#include <cuda_runtime.h>
#include <cstdint>

#define N_C 50000
#define N_V 100000
#define N_A 5000
#define E_C2V 1600000
#define E_A2V 1000000

// ---------------- static device scratch (no allocation) ----------------
__device__ __align__(16) float g_P_gv_v[N_V*32];
__device__ __align__(16) float g_P_hv_v[N_V*32];
__device__ __align__(16) float g_P_fv_v[N_V*32];
__device__ __align__(16) float g_P_ga_v[N_V*32];   // f_v_relu @ g_a_W1[14:46]
__device__ __align__(16) float g_P_gv_c[N_C*32];
__device__ __align__(16) float g_P_hv_a[N_A*32];
__device__ __align__(16) float g_P_ga_a[N_A*32];
__device__ __align__(16) float g_P_fa_a[N_A*32];
__device__ __align__(16) float g_acc_gv[N_V*32];
__device__ __align__(16) float g_acc_hv[N_V*32];
__device__ __align__(16) float g_acc_ga[N_A*32];
__device__ float g_cnt_gv[N_V];
__device__ float g_cnt_hv[N_V];
__device__ float g_cnt_ga[N_A];

// ---------------- f32x2 helpers (FFMA2 path: ptxas never emits these from C++) ----------------
static __device__ __forceinline__ unsigned long long pack_dup(float v){
  unsigned long long r; unsigned u = __float_as_uint(v);
  asm("mov.b64 %0, {%1,%1};" : "=l"(r) : "r"(u));
  return r;
}
static __device__ __forceinline__ unsigned long long pack2(float a, float b){
  unsigned long long r;
  asm("mov.b64 %0, {%1,%2};" : "=l"(r) : "r"(__float_as_uint(a)), "r"(__float_as_uint(b)));
  return r;
}
static __device__ __forceinline__ void fma2(unsigned long long& d,
                                            unsigned long long a, unsigned long long b){
  asm("fma.rn.f32x2 %0, %1, %2, %0;" : "+l"(d) : "l"(a), "l"(b));
}
static __device__ __forceinline__ float2 unpack2(unsigned long long v){
  unsigned lo, hi; asm("mov.b64 {%0,%1}, %2;" : "=r"(lo), "=r"(hi) : "l"(v));
  return make_float2(__uint_as_float(lo), __uint_as_float(hi));
}
static __device__ __forceinline__ void red2(float* p, float v0, float v1){
  asm volatile("red.global.add.v2.f32 [%0], {%1,%2};" :: "l"(p), "f"(v0), "f"(v1) : "memory");
}

// ---------------- zero accumulators ----------------
__global__ void k_zero(){
  int i = blockIdx.x*blockDim.x + threadIdx.x;
  int stride = gridDim.x*blockDim.x;
  for (int j=i;j<N_V*32;j+=stride){ g_acc_gv[j]=0.f; g_acc_hv[j]=0.f; }
  for (int j=i;j<N_V;j+=stride){ g_cnt_gv[j]=0.f; g_cnt_hv[j]=0.f; }
  for (int j=i;j<N_A*32;j+=stride) g_acc_ga[j]=0.f;
  for (int j=i;j<N_A;j+=stride) g_cnt_ga[j]=0.f;
}

// ---------------- fused per-node projections (up to 3 W1-slices per node type) ----------------
// which=0: v nodes (din=13) -> P_gv_v, P_hv_v, P_fv_v
// which=1: c nodes (din=14) -> P_gv_c
// which=2: a nodes (din=14) -> P_hv_a, P_ga_a, P_fa_a
__global__ void __launch_bounds__(256) k_pre3(
    const float* __restrict__ x, int n_nodes, int din, int nsets,
    const float* __restrict__ Wa, const float* __restrict__ Wb,
    const float* __restrict__ Wc, int which)
{
  __shared__ float s_w[3*14*32];
  const float* Ws[3] = {Wa, Wb, Wc};
  for (int m=0;m<nsets;m++)
    for (int i=threadIdx.x;i<din*32;i+=256) s_w[m*din*32+i] = Ws[m][i];
  __syncthreads();
  int node = blockIdx.x*256 + threadIdx.x;
  if (node >= n_nodes) return;
  float xr[14];
  const float* xp = x + (size_t)node*din;
  for (int k=0;k<din;k++) xr[k]=xp[k];
  for (int m=0;m<nsets;m++){
    float* out;
    if (which == 0) out = (m==0)?g_P_gv_v:((m==1)?g_P_hv_v:g_P_fv_v);
    else if (which == 1) out = g_P_gv_c;
    else out = (m==0)?g_P_hv_a:((m==1)?g_P_ga_a:g_P_fa_a);
    const float* w = &s_w[m*din*32];
    float* op = out + (size_t)node*32;
#pragma unroll
    for (int cg=0;cg<8;cg++){
      float4 a = make_float4(0.f,0.f,0.f,0.f);
      for (int k=0;k<din;k++){
        float4 ww = *(const float4*)&w[k*32+cg*4];
        a.x += xr[k]*ww.x; a.y += xr[k]*ww.y; a.z += xr[k]*ww.z; a.w += xr[k]*ww.w;
      }
      *(float4*)&op[cg*4] = a;
    }
  }
}

// ---------------- fused per-edge MLP (FFMA2 layer-2) + scatter-add ----------------
// mode 0: c2v / g_v : Ps=P_gv_c[s], Pt=P_gv_v[t], agg=t -> acc_gv
// mode 1: a2v / h_v : Ps=P_hv_a[s], Pt=P_hv_v[t], agg=t -> acc_hv
// mode 2: a2v / g_a : Ps=P_ga_a[s], Pt=P_ga_v[t], agg=s -> acc_ga
__global__ void __launch_bounds__(256) k_edge(
    int nedges, int mode,
    const int* __restrict__ src, const int* __restrict__ tgt,
    const float* __restrict__ attr,
    const float* __restrict__ W1, int rowoff_we,
    const float* __restrict__ b1,
    const float* __restrict__ W2, const float* __restrict__ b2)
{
  const float* Ps; const float* Pt; float* acc; float* cnt;
  if (mode == 0){ Ps=g_P_gv_c; Pt=g_P_gv_v; acc=g_acc_gv; cnt=g_cnt_gv; }
  else if (mode == 1){ Ps=g_P_hv_a; Pt=g_P_hv_v; acc=g_acc_hv; cnt=g_cnt_hv; }
  else { Ps=g_P_ga_a; Pt=g_P_ga_v; acc=g_acc_ga; cnt=g_cnt_ga; }

  __shared__ __align__(16) float s_W2[32*32];
  __shared__ float s_we[32], s_b1[32], s_b2[32];
  for (int i=threadIdx.x;i<32*32;i+=256) s_W2[i]=W2[i];
  if (threadIdx.x < 32){
    s_we[threadIdx.x] = W1[rowoff_we*32 + threadIdx.x];
    s_b1[threadIdx.x] = b1[threadIdx.x];
    s_b2[threadIdx.x] = b2[threadIdx.x];
  }
  __syncthreads();

  int e = blockIdx.x*256 + threadIdx.x;
  if (e >= nedges) return;
  int s = src[e], t = tgt[e];
  float at = attr[e];
  const float* ps = Ps + (size_t)s*32;
  const float* pt = Pt + (size_t)t*32;
  float h[32];
#pragma unroll
  for (int cg=0;cg<8;cg++){
    float4 a = *(const float4*)&ps[cg*4];
    float4 b = *(const float4*)&pt[cg*4];
    h[cg*4+0] = fmaxf(a.x + b.x + at*s_we[cg*4+0] + s_b1[cg*4+0], 0.f);
    h[cg*4+1] = fmaxf(a.y + b.y + at*s_we[cg*4+1] + s_b1[cg*4+1], 0.f);
    h[cg*4+2] = fmaxf(a.z + b.z + at*s_we[cg*4+2] + s_b1[cg*4+2], 0.f);
    h[cg*4+3] = fmaxf(a.w + b.w + at*s_we[cg*4+3] + s_b1[cg*4+3], 0.f);
  }

  // layer 2 with packed f32x2 FMA: 16 packed accumulators = 32 outputs
  unsigned long long accp[16];
#pragma unroll
  for (int p=0;p<16;p++) accp[p] = pack2(s_b2[2*p], s_b2[2*p+1]);
#pragma unroll
  for (int k=0;k<32;k++){
    unsigned long long hk = pack_dup(h[k]);
    const ulonglong2* wrow = (const ulonglong2*)&s_W2[k*32];
#pragma unroll
    for (int p2=0;p2<8;p2++){
      ulonglong2 w = wrow[p2];
      fma2(accp[2*p2],   hk, w.x);
      fma2(accp[2*p2+1], hk, w.y);
    }
  }

  int idx = (mode == 2) ? s : t;
  float* ac = acc + (size_t)idx*32;
#pragma unroll
  for (int p=0;p<16;p++){
    float2 v = unpack2(accp[p]);
    red2(ac + 2*p, fmaxf(v.x,0.f), fmaxf(v.y,0.f));
  }
  atomicAdd(cnt + idx, 1.0f);
}

// ---------------- f_v node MLP (77->32->32, relu out) fused with g_a projection ----------------
__global__ void __launch_bounds__(256) k_fv(
    const float* __restrict__ fvW1, const float* __restrict__ fvb1,
    const float* __restrict__ fvW2, const float* __restrict__ fvb2,
    const float* __restrict__ gaW1)
{
  __shared__ __align__(16) float s_W1[64*32];   // f_v W1 rows 13..76
  __shared__ __align__(16) float s_W2[32*32];
  __shared__ __align__(16) float s_Wg[32*32];   // g_a W1 rows 14..45
  __shared__ float s_b1[32], s_b2[32];
  for (int i=threadIdx.x;i<64*32;i+=256) s_W1[i]=fvW1[13*32+i];
  for (int i=threadIdx.x;i<32*32;i+=256){ s_W2[i]=fvW2[i]; s_Wg[i]=gaW1[14*32+i]; }
  if (threadIdx.x<32){ s_b1[threadIdx.x]=fvb1[threadIdx.x]; s_b2[threadIdx.x]=fvb2[threadIdx.x]; }
  __syncthreads();
  int n = blockIdx.x*256 + threadIdx.x;
  if (n >= N_V) return;
  float ig = 1.f/fmaxf(g_cnt_gv[n],1.f);
  float ih = 1.f/fmaxf(g_cnt_hv[n],1.f);

  unsigned long long hp[16];
#pragma unroll
  for (int p=0;p<16;p++) hp[p] = pack2(g_P_fv_v[(size_t)n*32+2*p] + s_b1[2*p],
                                       g_P_fv_v[(size_t)n*32+2*p+1] + s_b1[2*p+1]);
#pragma unroll 4
  for (int k=0;k<32;k++){
    unsigned long long g = pack_dup(g_acc_gv[(size_t)n*32+k]*ig);
    const ulonglong2* wrow = (const ulonglong2*)&s_W1[k*32];
#pragma unroll
    for (int p2=0;p2<8;p2++){ ulonglong2 w=wrow[p2]; fma2(hp[2*p2],g,w.x); fma2(hp[2*p2+1],g,w.y); }
  }
#pragma unroll 4
  for (int k=0;k<32;k++){
    unsigned long long g = pack_dup(g_acc_hv[(size_t)n*32+k]*ih);
    const ulonglong2* wrow = (const ulonglong2*)&s_W1[(32+k)*32];
#pragma unroll
    for (int p2=0;p2<8;p2++){ ulonglong2 w=wrow[p2]; fma2(hp[2*p2],g,w.x); fma2(hp[2*p2+1],g,w.y); }
  }
  float h[32];
#pragma unroll
  for (int p=0;p<16;p++){ float2 v=unpack2(hp[p]); h[2*p]=fmaxf(v.x,0.f); h[2*p+1]=fmaxf(v.y,0.f); }

  unsigned long long vp[16];
#pragma unroll
  for (int p=0;p<16;p++) vp[p] = pack2(s_b2[2*p], s_b2[2*p+1]);
#pragma unroll 4
  for (int k=0;k<32;k++){
    unsigned long long g = pack_dup(h[k]);
    const ulonglong2* wrow = (const ulonglong2*)&s_W2[k*32];
#pragma unroll
    for (int p2=0;p2<8;p2++){ ulonglong2 w=wrow[p2]; fma2(vp[2*p2],g,w.x); fma2(vp[2*p2+1],g,w.y); }
  }
  float v[32];
#pragma unroll
  for (int p=0;p<16;p++){ float2 t=unpack2(vp[p]); v[2*p]=fmaxf(t.x,0.f); v[2*p+1]=fmaxf(t.y,0.f); }

  unsigned long long op[16];
#pragma unroll
  for (int p=0;p<16;p++) op[p]=0ull;
#pragma unroll 4
  for (int k=0;k<32;k++){
    unsigned long long g = pack_dup(v[k]);
    const ulonglong2* wrow = (const ulonglong2*)&s_Wg[k*32];
#pragma unroll
    for (int p2=0;p2<8;p2++){ ulonglong2 w=wrow[p2]; fma2(op[2*p2],g,w.x); fma2(op[2*p2+1],g,w.y); }
  }
#pragma unroll
  for (int p=0;p<16;p++){
    float2 t=unpack2(op[p]);
    *(float2*)&g_P_ga_v[(size_t)n*32+2*p] = t;
  }
}

// ---------------- f_a node MLP (46->32->32, relu out) -> d_out ----------------
__global__ void __launch_bounds__(256) k_fa(
    const float* __restrict__ faW1, const float* __restrict__ fab1,
    const float* __restrict__ faW2, const float* __restrict__ fab2,
    float* __restrict__ out)
{
  __shared__ __align__(16) float s_W1[32*32];   // f_a W1 rows 14..45
  __shared__ __align__(16) float s_W2[32*32];
  __shared__ float s_b1[32], s_b2[32];
  for (int i=threadIdx.x;i<32*32;i+=256){ s_W1[i]=faW1[14*32+i]; s_W2[i]=faW2[i]; }
  if (threadIdx.x<32){ s_b1[threadIdx.x]=fab1[threadIdx.x]; s_b2[threadIdx.x]=fab2[threadIdx.x]; }
  __syncthreads();
  int n = blockIdx.x*256 + threadIdx.x;
  if (n >= N_A) return;
  float ig = 1.f/fmaxf(g_cnt_ga[n],1.f);
  float h[32];
#pragma unroll
  for (int c=0;c<32;c++) h[c] = g_P_fa_a[(size_t)n*32+c] + s_b1[c];
#pragma unroll 4
  for (int k=0;k<32;k++){
    float g = g_acc_ga[(size_t)n*32+k]*ig;
#pragma unroll
    for (int cg=0;cg<8;cg++){
      float4 w = *(const float4*)&s_W1[k*32+cg*4];
      h[cg*4+0]+=g*w.x; h[cg*4+1]+=g*w.y; h[cg*4+2]+=g*w.z; h[cg*4+3]+=g*w.w;
    }
  }
#pragma unroll
  for (int c=0;c<32;c++) h[c]=fmaxf(h[c],0.f);
  float v[32];
#pragma unroll
  for (int c=0;c<32;c++) v[c]=s_b2[c];
#pragma unroll 4
  for (int k=0;k<32;k++){
    float g = h[k];
#pragma unroll
    for (int cg=0;cg<8;cg++){
      float4 w = *(const float4*)&s_W2[k*32+cg*4];
      v[cg*4+0]+=g*w.x; v[cg*4+1]+=g*w.y; v[cg*4+2]+=g*w.z; v[cg*4+3]+=g*w.w;
    }
  }
#pragma unroll
  for (int cg=0;cg<8;cg++)
    *(float4*)&out[(size_t)n*32+cg*4] = make_float4(
        fmaxf(v[cg*4+0],0.f), fmaxf(v[cg*4+1],0.f),
        fmaxf(v[cg*4+2],0.f), fmaxf(v[cg*4+3],0.f));
}

// ---------------- launch ----------------
extern "C" void kernel_launch(void* const* d_in, const int* in_sizes, int n_in,
                              void* d_out, int out_size)
{
  const float* x_c   = (const float*)d_in[0];
  const float* x_v   = (const float*)d_in[1];
  const float* x_a   = (const float*)d_in[2];
  const int*   c2v_s = (const int*)d_in[3];
  const int*   c2v_t = (const int*)d_in[4];
  const int*   a2v_s = (const int*)d_in[5];
  const int*   a2v_t = (const int*)d_in[6];
  const float* ea_c2v = (const float*)d_in[7];
  const float* ea_a2v = (const float*)d_in[8];
  const float* gvW1 = (const float*)d_in[9];
  const float* gvb1 = (const float*)d_in[10];
  const float* gvW2 = (const float*)d_in[11];
  const float* gvb2 = (const float*)d_in[12];
  const float* hvW1 = (const float*)d_in[13];
  const float* hvb1 = (const float*)d_in[14];
  const float* hvW2 = (const float*)d_in[15];
  const float* hvb2 = (const float*)d_in[16];
  const float* fvW1 = (const float*)d_in[17];
  const float* fvb1 = (const float*)d_in[18];
  const float* fvW2 = (const float*)d_in[19];
  const float* fvb2 = (const float*)d_in[20];
  const float* gaW1 = (const float*)d_in[21];
  const float* gab1 = (const float*)d_in[22];
  const float* gaW2 = (const float*)d_in[23];
  const float* gab2 = (const float*)d_in[24];
  const float* faW1 = (const float*)d_in[25];
  const float* fab1 = (const float*)d_in[26];
  const float* faW2 = (const float*)d_in[27];
  const float* fab2 = (const float*)d_in[28];
  float* out = (float*)d_out;

  k_zero<<<1024, 256>>>();

  // fused projections
  k_pre3<<<(N_V+255)/256, 256>>>(x_v, N_V, 13, 3, gvW1, hvW1, fvW1, 0);
  k_pre3<<<(N_C+255)/256, 256>>>(x_c, N_C, 14, 1, gvW1 + 13*32, nullptr, nullptr, 1);
  k_pre3<<<(N_A+255)/256, 256>>>(x_a, N_A, 14, 3, hvW1 + 13*32, gaW1, faW1, 2);

  // edge passes (left-to-right)
  k_edge<<<(E_C2V+255)/256, 256>>>(E_C2V, 0, c2v_s, c2v_t, ea_c2v,
                                   gvW1, 27, gvb1, gvW2, gvb2);
  k_edge<<<(E_A2V+255)/256, 256>>>(E_A2V, 1, a2v_s, a2v_t, ea_a2v,
                                   hvW1, 27, hvb1, hvW2, hvb2);

  // variable-node update fused with g_a layer-1 projection
  k_fv<<<(N_V+255)/256, 256>>>(fvW1, fvb1, fvW2, fvb2, gaW1);

  // right-to-left edge pass
  k_edge<<<(E_A2V+255)/256, 256>>>(E_A2V, 2, a2v_s, a2v_t, ea_a2v,
                                   gaW1, 46, gab1, gaW2, gab2);

  // cut-node update -> output
  k_fa<<<(N_A+255)/256, 256>>>(faW1, fab1, faW2, fab2, out);
}

// round 4
// speedup vs baseline: 2.4504x; 2.4504x over previous
#include <cuda_runtime.h>
#include <cstdint>

#define N_C 50000
#define N_V 100000
#define N_A 5000
#define E_C2V 1600000
#define E_A2V 1000000

__device__ __align__(16) float g_P_gv_v[N_V*32];
__device__ __align__(16) float g_P_hv_v[N_V*32];
__device__ __align__(16) float g_P_fv_v[N_V*32];
__device__ __align__(16) float g_P_ga_v[N_V*32];
__device__ __align__(16) float g_P_gv_c[N_C*32];
__device__ __align__(16) float g_P_hv_a[N_A*32];
__device__ __align__(16) float g_P_ga_a[N_A*32];
__device__ __align__(16) float g_P_fa_a[N_A*32];
__device__ __align__(16) float g_acc_gv[N_V*32];
__device__ __align__(16) float g_acc_hv[N_V*32];
__device__ __align__(16) float g_acc_ga[N_A*32];
__device__ float g_cnt_gv[N_V];
__device__ float g_cnt_hv[N_V];
__device__ float g_cnt_ga[N_A];

static __device__ __forceinline__ unsigned f2tf(float f){
  unsigned u; asm("cvt.rna.tf32.f32 %0, %1;" : "=r"(u) : "f"(f)); return u;
}
static __device__ __forceinline__ void mma8(float d[4], const unsigned a[4],
                                            unsigned b0, unsigned b1){
  asm volatile("mma.sync.aligned.m16n8k8.row.col.f32.tf32.tf32.f32 "
      "{%0,%1,%2,%3},{%4,%5,%6,%7},{%8,%9},{%0,%1,%2,%3};"
      : "+f"(d[0]),"+f"(d[1]),"+f"(d[2]),"+f"(d[3])
      : "r"(a[0]),"r"(a[1]),"r"(a[2]),"r"(a[3]),"r"(b0),"r"(b1));
}
static __device__ __forceinline__ void red2(float* p, float v0, float v1){
  asm volatile("red.global.add.v2.f32 [%0], {%1,%2};" :: "l"(p), "f"(v0), "f"(v1) : "memory");
}

__global__ void k_zero(){
  int i = blockIdx.x*blockDim.x + threadIdx.x;
  int stride = gridDim.x*blockDim.x;
  for (int j=i;j<N_V*32;j+=stride){ g_acc_gv[j]=0.f; g_acc_hv[j]=0.f; }
  for (int j=i;j<N_V;j+=stride){ g_cnt_gv[j]=0.f; g_cnt_hv[j]=0.f; }
  for (int j=i;j<N_A*32;j+=stride) g_acc_ga[j]=0.f;
  for (int j=i;j<N_A;j+=stride) g_cnt_ga[j]=0.f;
}

// fused per-node projections (up to 3 W1 slices per node type)
__global__ void __launch_bounds__(256) k_pre3(
    const float* __restrict__ x, int n_nodes, int din, int nsets,
    const float* __restrict__ Wa, const float* __restrict__ Wb,
    const float* __restrict__ Wc, int which)
{
  __shared__ float s_w[3*14*32];
  const float* Ws[3] = {Wa, Wb, Wc};
  for (int m=0;m<nsets;m++)
    for (int i=threadIdx.x;i<din*32;i+=256) s_w[m*din*32+i] = Ws[m][i];
  __syncthreads();
  int node = blockIdx.x*256 + threadIdx.x;
  if (node >= n_nodes) return;
  float xr[14];
  const float* xp = x + (size_t)node*din;
  for (int k=0;k<din;k++) xr[k]=xp[k];
  for (int m=0;m<nsets;m++){
    float* out;
    if (which == 0) out = (m==0)?g_P_gv_v:((m==1)?g_P_hv_v:g_P_fv_v);
    else if (which == 1) out = g_P_gv_c;
    else out = (m==0)?g_P_hv_a:((m==1)?g_P_ga_a:g_P_fa_a);
    const float* w = &s_w[m*din*32];
    float* op = out + (size_t)node*32;
#pragma unroll
    for (int cg=0;cg<8;cg++){
      float4 a = make_float4(0.f,0.f,0.f,0.f);
      for (int k=0;k<din;k++){
        float4 ww = *(const float4*)&w[k*32+cg*4];
        a.x += xr[k]*ww.x; a.y += xr[k]*ww.y; a.z += xr[k]*ww.z; a.w += xr[k]*ww.w;
      }
      *(float4*)&op[cg*4] = a;
    }
  }
}

// per-edge MLP: factorized layer-1 + tf32 MMA layer-2 (hi/lo split B) + scatter
// mode 0: c2v/g_v agg=t; mode 1: a2v/h_v agg=t; mode 2: a2v/g_a agg=s
__global__ void __launch_bounds__(256) k_edge(
    int ntiles, int mode,
    const int* __restrict__ src, const int* __restrict__ tgt,
    const float* __restrict__ attr,
    const float* __restrict__ W1, int rowoff_we,
    const float* __restrict__ b1,
    const float* __restrict__ W2, const float* __restrict__ b2)
{
  const float* Ps; const float* Pt; float* acc; float* cnt;
  if (mode == 0){ Ps=g_P_gv_c; Pt=g_P_gv_v; acc=g_acc_gv; cnt=g_cnt_gv; }
  else if (mode == 1){ Ps=g_P_hv_a; Pt=g_P_hv_v; acc=g_acc_hv; cnt=g_cnt_hv; }
  else { Ps=g_P_ga_a; Pt=g_P_ga_v; acc=g_acc_ga; cnt=g_cnt_ga; }
  const int* agg = (mode == 2) ? src : tgt;

  const int lane = threadIdx.x & 31, q = lane & 3, g = lane >> 2;

  // W2 B-fragments, hi/lo tf32 split (loaded once per warp, L2-resident)
  unsigned bfh[4][4][2], bfl[4][4][2];
#pragma unroll
  for (int k=0;k<4;k++)
#pragma unroll
    for (int n=0;n<4;n++){
      float w0 = W2[(8*k+q)*32 + 8*n + g];
      float w1 = W2[(8*k+q+4)*32 + 8*n + g];
      unsigned h0 = f2tf(w0), h1 = f2tf(w1);
      bfh[k][n][0]=h0; bfh[k][n][1]=h1;
      bfl[k][n][0]=f2tf(w0 - __uint_as_float(h0));
      bfl[k][n][1]=f2tf(w1 - __uint_as_float(h1));
    }
  // per-thread copies of the 8 relevant rows of we/b1/b2
  float we[8], bb1[8], b2a[8], b2b[8];
#pragma unroll
  for (int k=0;k<4;k++){
    we[2*k]   = W1[rowoff_we*32 + 8*k+q];
    we[2*k+1] = W1[rowoff_we*32 + 8*k+q+4];
    bb1[2*k]  = b1[8*k+q];
    bb1[2*k+1]= b1[8*k+q+4];
    b2a[2*k]  = b2[8*k+2*q];   b2a[2*k+1] = b2[8*k+2*q+1];
  }
  (void)b2b;

  int warp = blockIdx.x*8 + (threadIdx.x>>5);
  int nw = gridDim.x*8;
  for (int tile = warp; tile < ntiles; tile += nw){
    int e0 = tile*16 + g, e1 = e0 + 8;
    int s0 = src[e0], t0 = tgt[e0];
    int s1 = src[e1], t1 = tgt[e1];
    float at0 = attr[e0], at1 = attr[e1];
    const float* ps0 = Ps + (size_t)s0*32; const float* pt0 = Pt + (size_t)t0*32;
    const float* ps1 = Ps + (size_t)s1*32; const float* pt1 = Pt + (size_t)t1*32;
    unsigned af[4][4];
#pragma unroll
    for (int k=0;k<4;k++){
      int c0 = 8*k+q, c1 = c0+4;
      af[k][0] = f2tf(fmaxf(pt0[c0]+ps0[c0]+at0*we[2*k]+bb1[2*k], 0.f));
      af[k][1] = f2tf(fmaxf(pt1[c0]+ps1[c0]+at1*we[2*k]+bb1[2*k], 0.f));
      af[k][2] = f2tf(fmaxf(pt0[c1]+ps0[c1]+at0*we[2*k+1]+bb1[2*k+1], 0.f));
      af[k][3] = f2tf(fmaxf(pt1[c1]+ps1[c1]+at1*we[2*k+1]+bb1[2*k+1], 0.f));
    }
    int i0 = (mode==2)?s0:t0, i1 = (mode==2)?s1:t1;
    float* a0 = acc + (size_t)i0*32;
    float* a1 = acc + (size_t)i1*32;
#pragma unroll
    for (int n=0;n<4;n++){
      float d[4] = {0.f,0.f,0.f,0.f};
#pragma unroll
      for (int k=0;k<4;k++) mma8(d, af[k], bfh[k][n][0], bfh[k][n][1]);
#pragma unroll
      for (int k=0;k<4;k++) mma8(d, af[k], bfl[k][n][0], bfl[k][n][1]);
      int c = 8*n + 2*q;
      red2(a0 + c, fmaxf(d[0]+b2a[2*n],0.f), fmaxf(d[1]+b2a[2*n+1],0.f));
      red2(a1 + c, fmaxf(d[2]+b2a[2*n],0.f), fmaxf(d[3]+b2a[2*n+1],0.f));
    }
    if (lane < 16) atomicAdd(cnt + agg[tile*16+lane], 1.0f);
  }
}

// f_v node MLP (77->32->32, relu out) fused with g_a layer-1 projection
__global__ void __launch_bounds__(256) k_fv(
    const float* __restrict__ fvW1, const float* __restrict__ fvb1,
    const float* __restrict__ fvW2, const float* __restrict__ fvb2,
    const float* __restrict__ gaW1)
{
  __shared__ __align__(16) float s_W1[64*32];
  __shared__ __align__(16) float s_W2[32*32];
  __shared__ __align__(16) float s_Wg[32*32];
  __shared__ float s_b1[32], s_b2[32];
  for (int i=threadIdx.x;i<64*32;i+=256) s_W1[i]=fvW1[13*32+i];
  for (int i=threadIdx.x;i<32*32;i+=256){ s_W2[i]=fvW2[i]; s_Wg[i]=gaW1[14*32+i]; }
  if (threadIdx.x<32){ s_b1[threadIdx.x]=fvb1[threadIdx.x]; s_b2[threadIdx.x]=fvb2[threadIdx.x]; }
  __syncthreads();
  int n = blockIdx.x*256 + threadIdx.x;
  if (n >= N_V) return;
  float ig = 1.f/fmaxf(g_cnt_gv[n],1.f);
  float ih = 1.f/fmaxf(g_cnt_hv[n],1.f);
  float h[32];
#pragma unroll
  for (int c=0;c<32;c++) h[c] = g_P_fv_v[(size_t)n*32+c] + s_b1[c];
#pragma unroll 4
  for (int k=0;k<32;k++){
    float g = g_acc_gv[(size_t)n*32+k]*ig;
#pragma unroll
    for (int cg=0;cg<8;cg++){
      float4 w = *(const float4*)&s_W1[k*32+cg*4];
      h[cg*4+0]+=g*w.x; h[cg*4+1]+=g*w.y; h[cg*4+2]+=g*w.z; h[cg*4+3]+=g*w.w;
    }
  }
#pragma unroll 4
  for (int k=0;k<32;k++){
    float g = g_acc_hv[(size_t)n*32+k]*ih;
#pragma unroll
    for (int cg=0;cg<8;cg++){
      float4 w = *(const float4*)&s_W1[(32+k)*32+cg*4];
      h[cg*4+0]+=g*w.x; h[cg*4+1]+=g*w.y; h[cg*4+2]+=g*w.z; h[cg*4+3]+=g*w.w;
    }
  }
#pragma unroll
  for (int c=0;c<32;c++) h[c]=fmaxf(h[c],0.f);
  float v[32];
#pragma unroll
  for (int c=0;c<32;c++) v[c]=s_b2[c];
#pragma unroll 4
  for (int k=0;k<32;k++){
    float g = h[k];
#pragma unroll
    for (int cg=0;cg<8;cg++){
      float4 w = *(const float4*)&s_W2[k*32+cg*4];
      v[cg*4+0]+=g*w.x; v[cg*4+1]+=g*w.y; v[cg*4+2]+=g*w.z; v[cg*4+3]+=g*w.w;
    }
  }
#pragma unroll
  for (int c=0;c<32;c++) v[c]=fmaxf(v[c],0.f);
  float o[32];
#pragma unroll
  for (int c=0;c<32;c++) o[c]=0.f;
#pragma unroll 4
  for (int k=0;k<32;k++){
    float g = v[k];
#pragma unroll
    for (int cg=0;cg<8;cg++){
      float4 w = *(const float4*)&s_Wg[k*32+cg*4];
      o[cg*4+0]+=g*w.x; o[cg*4+1]+=g*w.y; o[cg*4+2]+=g*w.z; o[cg*4+3]+=g*w.w;
    }
  }
#pragma unroll
  for (int cg=0;cg<8;cg++)
    *(float4*)&g_P_ga_v[(size_t)n*32+cg*4] = make_float4(o[cg*4],o[cg*4+1],o[cg*4+2],o[cg*4+3]);
}

// f_a node MLP (46->32->32, relu out) -> out
__global__ void __launch_bounds__(256) k_fa(
    const float* __restrict__ faW1, const float* __restrict__ fab1,
    const float* __restrict__ faW2, const float* __restrict__ fab2,
    float* __restrict__ out)
{
  __shared__ __align__(16) float s_W1[32*32];
  __shared__ __align__(16) float s_W2[32*32];
  __shared__ float s_b1[32], s_b2[32];
  for (int i=threadIdx.x;i<32*32;i+=256){ s_W1[i]=faW1[14*32+i]; s_W2[i]=faW2[i]; }
  if (threadIdx.x<32){ s_b1[threadIdx.x]=fab1[threadIdx.x]; s_b2[threadIdx.x]=fab2[threadIdx.x]; }
  __syncthreads();
  int n = blockIdx.x*256 + threadIdx.x;
  if (n >= N_A) return;
  float ig = 1.f/fmaxf(g_cnt_ga[n],1.f);
  float h[32];
#pragma unroll
  for (int c=0;c<32;c++) h[c] = g_P_fa_a[(size_t)n*32+c] + s_b1[c];
#pragma unroll 4
  for (int k=0;k<32;k++){
    float g = g_acc_ga[(size_t)n*32+k]*ig;
#pragma unroll
    for (int cg=0;cg<8;cg++){
      float4 w = *(const float4*)&s_W1[k*32+cg*4];
      h[cg*4+0]+=g*w.x; h[cg*4+1]+=g*w.y; h[cg*4+2]+=g*w.z; h[cg*4+3]+=g*w.w;
    }
  }
#pragma unroll
  for (int c=0;c<32;c++) h[c]=fmaxf(h[c],0.f);
  float v[32];
#pragma unroll
  for (int c=0;c<32;c++) v[c]=s_b2[c];
#pragma unroll 4
  for (int k=0;k<32;k++){
    float g = h[k];
#pragma unroll
    for (int cg=0;cg<8;cg++){
      float4 w = *(const float4*)&s_W2[k*32+cg*4];
      v[cg*4+0]+=g*w.x; v[cg*4+1]+=g*w.y; v[cg*4+2]+=g*w.z; v[cg*4+3]+=g*w.w;
    }
  }
#pragma unroll
  for (int cg=0;cg<8;cg++)
    *(float4*)&out[(size_t)n*32+cg*4] = make_float4(
        fmaxf(v[cg*4+0],0.f), fmaxf(v[cg*4+1],0.f),
        fmaxf(v[cg*4+2],0.f), fmaxf(v[cg*4+3],0.f));
}

extern "C" void kernel_launch(void* const* d_in, const int* in_sizes, int n_in,
                              void* d_out, int out_size)
{
  const float* x_c   = (const float*)d_in[0];
  const float* x_v   = (const float*)d_in[1];
  const float* x_a   = (const float*)d_in[2];
  const int*   c2v_s = (const int*)d_in[3];
  const int*   c2v_t = (const int*)d_in[4];
  const int*   a2v_s = (const int*)d_in[5];
  const int*   a2v_t = (const int*)d_in[6];
  const float* ea_c2v = (const float*)d_in[7];
  const float* ea_a2v = (const float*)d_in[8];
  const float* gvW1 = (const float*)d_in[9];
  const float* gvb1 = (const float*)d_in[10];
  const float* gvW2 = (const float*)d_in[11];
  const float* gvb2 = (const float*)d_in[12];
  const float* hvW1 = (const float*)d_in[13];
  const float* hvb1 = (const float*)d_in[14];
  const float* hvW2 = (const float*)d_in[15];
  const float* hvb2 = (const float*)d_in[16];
  const float* fvW1 = (const float*)d_in[17];
  const float* fvb1 = (const float*)d_in[18];
  const float* fvW2 = (const float*)d_in[19];
  const float* fvb2 = (const float*)d_in[20];
  const float* gaW1 = (const float*)d_in[21];
  const float* gab1 = (const float*)d_in[22];
  const float* gaW2 = (const float*)d_in[23];
  const float* gab2 = (const float*)d_in[24];
  const float* faW1 = (const float*)d_in[25];
  const float* fab1 = (const float*)d_in[26];
  const float* faW2 = (const float*)d_in[27];
  const float* fab2 = (const float*)d_in[28];
  float* out = (float*)d_out;

  k_zero<<<1024, 256>>>();

  k_pre3<<<(N_V+255)/256, 256>>>(x_v, N_V, 13, 3, gvW1, hvW1, fvW1, 0);
  k_pre3<<<(N_C+255)/256, 256>>>(x_c, N_C, 14, 1, gvW1 + 13*32, nullptr, nullptr, 1);
  k_pre3<<<(N_A+255)/256, 256>>>(x_a, N_A, 14, 3, hvW1 + 13*32, gaW1, faW1, 2);

  k_edge<<<1024, 256>>>(E_C2V/16, 0, c2v_s, c2v_t, ea_c2v, gvW1, 27, gvb1, gvW2, gvb2);
  k_edge<<<1024, 256>>>(E_A2V/16, 1, a2v_s, a2v_t, ea_a2v, hvW1, 27, hvb1, hvW2, hvb2);

  k_fv<<<(N_V+255)/256, 256>>>(fvW1, fvb1, fvW2, fvb2, gaW1);

  k_edge<<<1024, 256>>>(E_A2V/16, 2, a2v_s, a2v_t, ea_a2v, gaW1, 46, gab1, gaW2, gab2);

  k_fa<<<(N_A+255)/256, 256>>>(faW1, fab1, faW2, fab2, out);
}

// round 5
// speedup vs baseline: 2.5267x; 1.0311x over previous
#include <cuda_runtime.h>
#include <cstdint>

#define N_C 50000
#define N_V 100000
#define N_A 5000
#define E_C2V 1600000
#define E_A2V 1000000

__device__ __align__(16) float g_P_gv_v[N_V*32];
__device__ __align__(16) float g_P_hv_v[N_V*32];
__device__ __align__(16) float g_P_fv_v[N_V*32];
__device__ __align__(16) float g_P_ga_v[N_V*32];
__device__ __align__(16) float g_P_gv_c[N_C*32];
__device__ __align__(16) float g_P_hv_a[N_A*32];
__device__ __align__(16) float g_P_ga_a[N_A*32];
__device__ __align__(16) float g_P_fa_a[N_A*32];
__device__ __align__(16) float g_acc_gv[N_V*32];
__device__ __align__(16) float g_acc_hv[N_V*32];
__device__ __align__(16) float g_acc_ga[N_A*32];
__device__ float g_cnt_gv[N_V];
__device__ float g_cnt_hv[N_V];
__device__ float g_cnt_ga[N_A];

static __device__ __forceinline__ unsigned f2tf(float f){
  unsigned u; asm("cvt.rna.tf32.f32 %0, %1;" : "=r"(u) : "f"(f)); return u;
}
static __device__ __forceinline__ void mma8(float d[4], const unsigned a[4],
                                            unsigned b0, unsigned b1){
  asm volatile("mma.sync.aligned.m16n8k8.row.col.f32.tf32.tf32.f32 "
      "{%0,%1,%2,%3},{%4,%5,%6,%7},{%8,%9},{%0,%1,%2,%3};"
      : "+f"(d[0]),"+f"(d[1]),"+f"(d[2]),"+f"(d[3])
      : "r"(a[0]),"r"(a[1]),"r"(a[2]),"r"(a[3]),"r"(b0),"r"(b1));
}
static __device__ __forceinline__ void red4(float* p, float a, float b, float c, float d){
  asm volatile("red.global.add.v4.f32 [%0], {%1,%2,%3,%4};"
               :: "l"(p), "f"(a), "f"(b), "f"(c), "f"(d) : "memory");
}

__global__ void k_zero(){
  int i = blockIdx.x*blockDim.x + threadIdx.x;
  int stride = gridDim.x*blockDim.x;
  float4 z = make_float4(0.f,0.f,0.f,0.f);
  for (int j=i;j<N_V*8;j+=stride){ ((float4*)g_acc_gv)[j]=z; ((float4*)g_acc_hv)[j]=z; }
  for (int j=i;j<N_V;j+=stride){ g_cnt_gv[j]=0.f; g_cnt_hv[j]=0.f; }
  for (int j=i;j<N_A*8;j+=stride) ((float4*)g_acc_ga)[j]=z;
  for (int j=i;j<N_A;j+=stride) g_cnt_ga[j]=0.f;
}

// fused per-node projections (up to 3 W1 slices per node type)
__global__ void __launch_bounds__(256) k_pre3(
    const float* __restrict__ x, int n_nodes, int din, int nsets,
    const float* __restrict__ Wa, const float* __restrict__ Wb,
    const float* __restrict__ Wc, int which)
{
  __shared__ float s_w[3*14*32];
  const float* Ws[3] = {Wa, Wb, Wc};
  for (int m=0;m<nsets;m++)
    for (int i=threadIdx.x;i<din*32;i+=256) s_w[m*din*32+i] = Ws[m][i];
  __syncthreads();
  int node = blockIdx.x*256 + threadIdx.x;
  if (node >= n_nodes) return;
  float xr[14];
  const float* xp = x + (size_t)node*din;
  for (int k=0;k<din;k++) xr[k]=xp[k];
  for (int m=0;m<nsets;m++){
    float* out;
    if (which == 0) out = (m==0)?g_P_gv_v:((m==1)?g_P_hv_v:g_P_fv_v);
    else if (which == 1) out = g_P_gv_c;
    else out = (m==0)?g_P_hv_a:((m==1)?g_P_ga_a:g_P_fa_a);
    const float* w = &s_w[m*din*32];
    float* op = out + (size_t)node*32;
#pragma unroll
    for (int cg=0;cg<8;cg++){
      float4 a = make_float4(0.f,0.f,0.f,0.f);
      for (int k=0;k<din;k++){
        float4 ww = *(const float4*)&w[k*32+cg*4];
        a.x += xr[k]*ww.x; a.y += xr[k]*ww.y; a.z += xr[k]*ww.z; a.w += xr[k]*ww.w;
      }
      *(float4*)&op[cg*4] = a;
    }
  }
}

// per-edge MLP: factorized layer-1 + tf32 MMA layer-2 + shfl-assembled red.v4 scatter
// mode 0: c2v/g_v agg=t; mode 1: a2v/h_v agg=t; mode 2: a2v/g_a agg=s
__global__ void __launch_bounds__(256) k_edge(
    int ntiles, int mode,
    const int* __restrict__ src, const int* __restrict__ tgt,
    const float* __restrict__ attr,
    const float* __restrict__ W1, int rowoff_we,
    const float* __restrict__ b1,
    const float* __restrict__ W2, const float* __restrict__ b2)
{
  const float* Ps; const float* Pt; float* acc; float* cnt;
  if (mode == 0){ Ps=g_P_gv_c; Pt=g_P_gv_v; acc=g_acc_gv; cnt=g_cnt_gv; }
  else if (mode == 1){ Ps=g_P_hv_a; Pt=g_P_hv_v; acc=g_acc_hv; cnt=g_cnt_hv; }
  else { Ps=g_P_ga_a; Pt=g_P_ga_v; acc=g_acc_ga; cnt=g_cnt_ga; }
  const int* agg = (mode == 2) ? src : tgt;

  const int lane = threadIdx.x & 31, q = lane & 3, g = lane >> 2;
  const int lowq = (q & 1) == 0;        // takes n-groups {0,1}, else {2,3}
  const int colh = 4*(q >> 1);          // low/high 4-col half within n-group

  // W2 B-fragments, tf32 (hi only; lo-split dropped — error well under gate)
  unsigned bf[4][4][2];
#pragma unroll
  for (int k=0;k<4;k++)
#pragma unroll
    for (int n=0;n<4;n++){
      bf[k][n][0] = f2tf(W2[(8*k+q)*32 + 8*n + g]);
      bf[k][n][1] = f2tf(W2[(8*k+q+4)*32 + 8*n + g]);
    }
  // per-thread rows of we/b1 (A-fragment cols) and b2 groups (output cols)
  float we[8], bb1[8];
#pragma unroll
  for (int k=0;k<4;k++){
    we[2*k]   = W1[rowoff_we*32 + 8*k+q];
    we[2*k+1] = W1[rowoff_we*32 + 8*k+q+4];
    bb1[2*k]  = b1[8*k+q];
    bb1[2*k+1]= b1[8*k+q+4];
  }
  float b2g[2][4];
#pragma unroll
  for (int j=0;j<2;j++){
    int n = lowq ? j : 2+j;
#pragma unroll
    for (int i=0;i<4;i++) b2g[j][i] = b2[8*n + colh + i];
  }

  int warp = blockIdx.x*8 + (threadIdx.x>>5);
  int nw = gridDim.x*8;
  for (int tile = warp; tile < ntiles; tile += nw){
    int e0 = tile*16 + g, e1 = e0 + 8;
    int s0 = src[e0], t0 = tgt[e0];
    int s1 = src[e1], t1 = tgt[e1];
    float at0 = attr[e0], at1 = attr[e1];
    const float* ps0 = Ps + (size_t)s0*32; const float* pt0 = Pt + (size_t)t0*32;
    const float* ps1 = Ps + (size_t)s1*32; const float* pt1 = Pt + (size_t)t1*32;
    unsigned af[4][4];
#pragma unroll
    for (int k=0;k<4;k++){
      int c0 = 8*k+q, c1 = c0+4;
      af[k][0] = f2tf(fmaxf(pt0[c0]+ps0[c0]+at0*we[2*k]+bb1[2*k], 0.f));
      af[k][1] = f2tf(fmaxf(pt1[c0]+ps1[c0]+at1*we[2*k]+bb1[2*k], 0.f));
      af[k][2] = f2tf(fmaxf(pt0[c1]+ps0[c1]+at0*we[2*k+1]+bb1[2*k+1], 0.f));
      af[k][3] = f2tf(fmaxf(pt1[c1]+ps1[c1]+at1*we[2*k+1]+bb1[2*k+1], 0.f));
    }
    // all 4 n-tiles of D before scatter
    float d[4][4];
#pragma unroll
    for (int n=0;n<4;n++){
      d[n][0]=0.f; d[n][1]=0.f; d[n][2]=0.f; d[n][3]=0.f;
#pragma unroll
      for (int k=0;k<4;k++) mma8(d[n], af[k], bf[k][n][0], bf[k][n][1]);
    }
    // butterfly(xor 1) exchange: assemble 4 contiguous cols per thread
    float sh[4][4];
#pragma unroll
    for (int n=0;n<4;n++)
#pragma unroll
      for (int j=0;j<4;j++) sh[n][j] = __shfl_xor_sync(0xffffffffu, d[n][j], 1);

    int i0 = (mode==2)?s0:t0, i1 = (mode==2)?s1:t1;
    float* a0 = acc + (size_t)i0*32;
    float* a1 = acc + (size_t)i1*32;
#pragma unroll
    for (int j=0;j<2;j++){
      int n = lowq ? j : 2+j;
      int c = 8*n + colh;
      float v0,v1,v2,v3, w0,w1,w2,w3;
      if (lowq){ v0=d[n][0]; v1=d[n][1]; v2=sh[n][0]; v3=sh[n][1];
                 w0=d[n][2]; w1=d[n][3]; w2=sh[n][2]; w3=sh[n][3]; }
      else     { v0=sh[n][0]; v1=sh[n][1]; v2=d[n][0]; v3=d[n][1];
                 w0=sh[n][2]; w1=sh[n][3]; w2=d[n][2]; w3=d[n][3]; }
      red4(a0 + c, fmaxf(v0+b2g[j][0],0.f), fmaxf(v1+b2g[j][1],0.f),
                   fmaxf(v2+b2g[j][2],0.f), fmaxf(v3+b2g[j][3],0.f));
      red4(a1 + c, fmaxf(w0+b2g[j][0],0.f), fmaxf(w1+b2g[j][1],0.f),
                   fmaxf(w2+b2g[j][2],0.f), fmaxf(w3+b2g[j][3],0.f));
    }
    if (lane < 16) atomicAdd(cnt + agg[tile*16+lane], 1.0f);
  }
}

// f_v node MLP (77->32->32, relu out) fused with g_a layer-1 projection
__global__ void __launch_bounds__(256) k_fv(
    const float* __restrict__ fvW1, const float* __restrict__ fvb1,
    const float* __restrict__ fvW2, const float* __restrict__ fvb2,
    const float* __restrict__ gaW1)
{
  __shared__ __align__(16) float s_W1[64*32];
  __shared__ __align__(16) float s_W2[32*32];
  __shared__ __align__(16) float s_Wg[32*32];
  __shared__ float s_b1[32], s_b2[32];
  for (int i=threadIdx.x;i<64*32;i+=256) s_W1[i]=fvW1[13*32+i];
  for (int i=threadIdx.x;i<32*32;i+=256){ s_W2[i]=fvW2[i]; s_Wg[i]=gaW1[14*32+i]; }
  if (threadIdx.x<32){ s_b1[threadIdx.x]=fvb1[threadIdx.x]; s_b2[threadIdx.x]=fvb2[threadIdx.x]; }
  __syncthreads();
  int n = blockIdx.x*256 + threadIdx.x;
  if (n >= N_V) return;
  float ig = 1.f/fmaxf(g_cnt_gv[n],1.f);
  float ih = 1.f/fmaxf(g_cnt_hv[n],1.f);
  float h[32];
#pragma unroll
  for (int c=0;c<32;c++) h[c] = g_P_fv_v[(size_t)n*32+c] + s_b1[c];
#pragma unroll 4
  for (int k=0;k<32;k++){
    float g = g_acc_gv[(size_t)n*32+k]*ig;
#pragma unroll
    for (int cg=0;cg<8;cg++){
      float4 w = *(const float4*)&s_W1[k*32+cg*4];
      h[cg*4+0]+=g*w.x; h[cg*4+1]+=g*w.y; h[cg*4+2]+=g*w.z; h[cg*4+3]+=g*w.w;
    }
  }
#pragma unroll 4
  for (int k=0;k<32;k++){
    float g = g_acc_hv[(size_t)n*32+k]*ih;
#pragma unroll
    for (int cg=0;cg<8;cg++){
      float4 w = *(const float4*)&s_W1[(32+k)*32+cg*4];
      h[cg*4+0]+=g*w.x; h[cg*4+1]+=g*w.y; h[cg*4+2]+=g*w.z; h[cg*4+3]+=g*w.w;
    }
  }
#pragma unroll
  for (int c=0;c<32;c++) h[c]=fmaxf(h[c],0.f);
  float v[32];
#pragma unroll
  for (int c=0;c<32;c++) v[c]=s_b2[c];
#pragma unroll 4
  for (int k=0;k<32;k++){
    float g = h[k];
#pragma unroll
    for (int cg=0;cg<8;cg++){
      float4 w = *(const float4*)&s_W2[k*32+cg*4];
      v[cg*4+0]+=g*w.x; v[cg*4+1]+=g*w.y; v[cg*4+2]+=g*w.z; v[cg*4+3]+=g*w.w;
    }
  }
#pragma unroll
  for (int c=0;c<32;c++) v[c]=fmaxf(v[c],0.f);
  float o[32];
#pragma unroll
  for (int c=0;c<32;c++) o[c]=0.f;
#pragma unroll 4
  for (int k=0;k<32;k++){
    float g = v[k];
#pragma unroll
    for (int cg=0;cg<8;cg++){
      float4 w = *(const float4*)&s_Wg[k*32+cg*4];
      o[cg*4+0]+=g*w.x; o[cg*4+1]+=g*w.y; o[cg*4+2]+=g*w.z; o[cg*4+3]+=g*w.w;
    }
  }
#pragma unroll
  for (int cg=0;cg<8;cg++)
    *(float4*)&g_P_ga_v[(size_t)n*32+cg*4] = make_float4(o[cg*4],o[cg*4+1],o[cg*4+2],o[cg*4+3]);
}

// f_a node MLP (46->32->32, relu out) -> out
__global__ void __launch_bounds__(256) k_fa(
    const float* __restrict__ faW1, const float* __restrict__ fab1,
    const float* __restrict__ faW2, const float* __restrict__ fab2,
    float* __restrict__ out)
{
  __shared__ __align__(16) float s_W1[32*32];
  __shared__ __align__(16) float s_W2[32*32];
  __shared__ float s_b1[32], s_b2[32];
  for (int i=threadIdx.x;i<32*32;i+=256){ s_W1[i]=faW1[14*32+i]; s_W2[i]=faW2[i]; }
  if (threadIdx.x<32){ s_b1[threadIdx.x]=fab1[threadIdx.x]; s_b2[threadIdx.x]=fab2[threadIdx.x]; }
  __syncthreads();
  int n = blockIdx.x*256 + threadIdx.x;
  if (n >= N_A) return;
  float ig = 1.f/fmaxf(g_cnt_ga[n],1.f);
  float h[32];
#pragma unroll
  for (int c=0;c<32;c++) h[c] = g_P_fa_a[(size_t)n*32+c] + s_b1[c];
#pragma unroll 4
  for (int k=0;k<32;k++){
    float g = g_acc_ga[(size_t)n*32+k]*ig;
#pragma unroll
    for (int cg=0;cg<8;cg++){
      float4 w = *(const float4*)&s_W1[k*32+cg*4];
      h[cg*4+0]+=g*w.x; h[cg*4+1]+=g*w.y; h[cg*4+2]+=g*w.z; h[cg*4+3]+=g*w.w;
    }
  }
#pragma unroll
  for (int c=0;c<32;c++) h[c]=fmaxf(h[c],0.f);
  float v[32];
#pragma unroll
  for (int c=0;c<32;c++) v[c]=s_b2[c];
#pragma unroll 4
  for (int k=0;k<32;k++){
    float g = h[k];
#pragma unroll
    for (int cg=0;cg<8;cg++){
      float4 w = *(const float4*)&s_W2[k*32+cg*4];
      v[cg*4+0]+=g*w.x; v[cg*4+1]+=g*w.y; v[cg*4+2]+=g*w.z; v[cg*4+3]+=g*w.w;
    }
  }
#pragma unroll
  for (int cg=0;cg<8;cg++)
    *(float4*)&out[(size_t)n*32+cg*4] = make_float4(
        fmaxf(v[cg*4+0],0.f), fmaxf(v[cg*4+1],0.f),
        fmaxf(v[cg*4+2],0.f), fmaxf(v[cg*4+3],0.f));
}

extern "C" void kernel_launch(void* const* d_in, const int* in_sizes, int n_in,
                              void* d_out, int out_size)
{
  const float* x_c   = (const float*)d_in[0];
  const float* x_v   = (const float*)d_in[1];
  const float* x_a   = (const float*)d_in[2];
  const int*   c2v_s = (const int*)d_in[3];
  const int*   c2v_t = (const int*)d_in[4];
  const int*   a2v_s = (const int*)d_in[5];
  const int*   a2v_t = (const int*)d_in[6];
  const float* ea_c2v = (const float*)d_in[7];
  const float* ea_a2v = (const float*)d_in[8];
  const float* gvW1 = (const float*)d_in[9];
  const float* gvb1 = (const float*)d_in[10];
  const float* gvW2 = (const float*)d_in[11];
  const float* gvb2 = (const float*)d_in[12];
  const float* hvW1 = (const float*)d_in[13];
  const float* hvb1 = (const float*)d_in[14];
  const float* hvW2 = (const float*)d_in[15];
  const float* hvb2 = (const float*)d_in[16];
  const float* fvW1 = (const float*)d_in[17];
  const float* fvb1 = (const float*)d_in[18];
  const float* fvW2 = (const float*)d_in[19];
  const float* fvb2 = (const float*)d_in[20];
  const float* gaW1 = (const float*)d_in[21];
  const float* gab1 = (const float*)d_in[22];
  const float* gaW2 = (const float*)d_in[23];
  const float* gab2 = (const float*)d_in[24];
  const float* faW1 = (const float*)d_in[25];
  const float* fab1 = (const float*)d_in[26];
  const float* faW2 = (const float*)d_in[27];
  const float* fab2 = (const float*)d_in[28];
  float* out = (float*)d_out;

  k_zero<<<2048, 256>>>();

  k_pre3<<<(N_V+255)/256, 256>>>(x_v, N_V, 13, 3, gvW1, hvW1, fvW1, 0);
  k_pre3<<<(N_C+255)/256, 256>>>(x_c, N_C, 14, 1, gvW1 + 13*32, nullptr, nullptr, 1);
  k_pre3<<<(N_A+255)/256, 256>>>(x_a, N_A, 14, 3, hvW1 + 13*32, gaW1, faW1, 2);

  k_edge<<<1024, 256>>>(E_C2V/16, 0, c2v_s, c2v_t, ea_c2v, gvW1, 27, gvb1, gvW2, gvb2);
  k_edge<<<1024, 256>>>(E_A2V/16, 1, a2v_s, a2v_t, ea_a2v, hvW1, 27, hvb1, hvW2, hvb2);

  k_fv<<<(N_V+255)/256, 256>>>(fvW1, fvb1, fvW2, fvb2, gaW1);

  k_edge<<<1024, 256>>>(E_A2V/16, 2, a2v_s, a2v_t, ea_a2v, gaW1, 46, gab1, gaW2, gab2);

  k_fa<<<(N_A+255)/256, 256>>>(faW1, fab1, faW2, fab2, out);
}